// round 13
// baseline (speedup 1.0000x reference)
#include <cuda_runtime.h>
#include <cuda_fp16.h>
#include <math.h>
#include <stdint.h>

// Problem constants
#define T_DIM   4
#define H_DIM   256
#define W_DIM   256
#define C_DIM   256
#define PS      8
#define NH      8
#define HD      32
#define NTOK    64
#define NWIN    4096
#define NROWS   (NWIN * NTOK)

// Scratch (allocation-free rule: __device__ globals)
__device__ __half g_q[(size_t)NWIN * NH * NTOK * HD]; // [n][h][p][d]
__device__ __half g_k[(size_t)NWIN * NH * NTOK * HD];
__device__ __half g_v[(size_t)NWIN * NH * NTOK * HD];
__device__ __half g_o[(size_t)NROWS * C_DIM];         // [n][p][c]
__device__ __half g_wbt[768 * 256];                   // [n][k]: [wq*sc|wkv]^T
__device__ __half g_pwt[256 * 256];                   // [n][k]: proj_w^T
__device__ float  g_mw[64 * 768];                     // fp32: modu@W + bias (q scaled)
__device__ float  g_rptT[8 * 225];                    // bias table transposed [h][225]

// ---------------------------------------------------------------------------
__device__ __forceinline__ void mma_f16(float* c, const uint32_t* a, const uint32_t* b) {
    asm volatile(
        "mma.sync.aligned.m16n8k16.row.col.f32.f16.f16.f32 "
        "{%0,%1,%2,%3}, {%4,%5,%6,%7}, {%8,%9}, {%0,%1,%2,%3};"
        : "+f"(c[0]), "+f"(c[1]), "+f"(c[2]), "+f"(c[3])
        : "r"(a[0]), "r"(a[1]), "r"(a[2]), "r"(a[3]), "r"(b[0]), "r"(b[1]));
}
__device__ __forceinline__ void ldsm4(uint32_t& r0, uint32_t& r1, uint32_t& r2,
                                      uint32_t& r3, uint32_t addr) {
    asm volatile("ldmatrix.sync.aligned.m8n8.x4.shared.b16 {%0,%1,%2,%3}, [%4];"
        : "=r"(r0), "=r"(r1), "=r"(r2), "=r"(r3) : "r"(addr));
}
__device__ __forceinline__ void ldsm4t(uint32_t& r0, uint32_t& r1, uint32_t& r2,
                                       uint32_t& r3, uint32_t addr) {
    asm volatile("ldmatrix.sync.aligned.m8n8.x4.trans.shared.b16 {%0,%1,%2,%3}, [%4];"
        : "=r"(r0), "=r"(r1), "=r"(r2), "=r"(r3) : "r"(addr));
}
__device__ __forceinline__ void cp16(uint32_t s, const void* g) {
    asm volatile("cp.async.ca.shared.global [%0], [%1], 16;" :: "r"(s), "l"(g));
}
#define CP_COMMIT() asm volatile("cp.async.commit_group;" ::: "memory")
#define CP_WAIT(n)  asm volatile("cp.async.wait_group %0;" :: "n"(n) : "memory")

#define STRB 80                       // B / attn row stride bytes
// qkv smem: A resident + 4-stage B ring
#define ASTR 528                      // A row stride bytes (512 + 16 pad)
#define A_BYTES (128 * ASTR)          // 67584
#define BT_BYTES (128 * STRB)         // 10240 per B stage
#define QKV_SMEM (A_BYTES + 4 * BT_BYTES)   // 108544

// proj smem (3-stage, both operands streamed)
#define NSTG 3
#define TILE_STG (128 * STRB)
#define PB_BASE  (NSTG * TILE_STG)
#define PROJ_SMEM (2 * NSTG * TILE_STG)     // 61440

// ---------------------------------------------------------------------------
// Prep 1: weights -> fp16 transposed [n][k] (q-scale folded) + rpt transpose
// grid = 1032 x 256
// ---------------------------------------------------------------------------
__global__ __launch_bounds__(256) void prep_w(
    const float* __restrict__ wq, const float* __restrict__ wkv,
    const float* __restrict__ pw, const float* __restrict__ rpt)
{
    const float sc = 0.1767766952966369f; // 1/sqrt(32)
    int idx = blockIdx.x * 256 + threadIdx.x;
    if (idx < 196608) {
        int n = idx >> 8, k = idx & 255;
        float v = (n < 256) ? wq[k * 256 + n] * sc : wkv[k * 512 + (n - 256)];
        g_wbt[idx] = __float2half_rn(v);
    } else if (idx < 262144) {
        int j = idx - 196608;
        int n = j >> 8, k = j & 255;
        g_pwt[j] = __float2half_rn(pw[k * 256 + n]);
    } else {
        int j2 = idx - 262144;
        if (j2 < 1800) {
            int h = j2 / 225, i = j2 % 225;
            g_rptT[h * 225 + i] = rpt[(size_t)i * NH + h];
        }
    }
}

// ---------------------------------------------------------------------------
// Prep 2: modw[p][c] = modu[p]@W + bias (q part scaled). grid (64, 3) x 256.
// ---------------------------------------------------------------------------
__global__ __launch_bounds__(256) void prep_modw(
    const float* __restrict__ modu,
    const float* __restrict__ wq,  const float* __restrict__ bq,
    const float* __restrict__ wkv, const float* __restrict__ bkv)
{
    __shared__ float m[256];
    const int p = blockIdx.x;
    m[threadIdx.x] = modu[p * 256 + threadIdx.x];
    __syncthreads();
    const float sc = 0.1767766952966369f;
    const int c = blockIdx.y * 256 + threadIdx.x;
    float s = 0.f;
    if (c < 256) {
        for (int k = 0; k < 256; k++) s = fmaf(m[k], wq[k * 256 + c], s);
        s = (s + bq[c]) * sc;
    } else {
        int cc = c - 256;
        for (int k = 0; k < 256; k++) s = fmaf(m[k], wkv[k * 512 + cc], s);
        s += bkv[cc];
    }
    g_mw[p * 768 + c] = s;
}

// ---------------------------------------------------------------------------
// Kernel A (FP16 MMA, A-resident): X @ [wq|wkv], all 768 cols per CTA.
// grid = 2048 (2 windows per CTA).
// ---------------------------------------------------------------------------
__global__ __launch_bounds__(256, 2) void qkv_tc(const float* __restrict__ vid)
{
    extern __shared__ uint32_t smem[];
    const uint32_t su = (uint32_t)__cvta_generic_to_shared(smem);

    const int tid  = threadIdx.x;
    const int lane = tid & 31;
    const int warp = tid >> 5;
    const int wm   = warp >> 2;
    const int wn   = warp & 3;
    const int n2   = blockIdx.x * 2;

    const int r0 = tid >> 2;
    const int kc = tid & 3;
    const uint32_t bo0 = (uint32_t)(r0 * STRB + kc * 16);
    const uint32_t bo1 = (uint32_t)((r0 + 64) * STRB + kc * 16);

#pragma unroll
    for (int s = 0; s < 3; s++) {
        const __half* b0 = g_wbt + (size_t)r0 * 256 + s * 32 + kc * 8;
        cp16(su + A_BYTES + s * BT_BYTES + bo0, b0);
        cp16(su + A_BYTES + s * BT_BYTES + bo1, b0 + (size_t)64 * 256);
        CP_COMMIT();
    }

    // A load: fp32 vid -> fp16 resident smem
    {
        const int ar = tid & 127;
        const int ah = tid >> 7;
        const int win = n2 + (ar >> 6);
        const int p   = ar & 63;
        const int ti = win >> 10, wh = (win >> 5) & 31, ww = win & 31;
        const float* src = vid +
            (((size_t)ti * H_DIM + wh * PS + (p >> 3)) * W_DIM + ww * PS + (p & 7)) * C_DIM
            + ah * 128;
        const uint32_t adst = su + (uint32_t)(ar * ASTR + ah * 256);
#pragma unroll
        for (int j = 0; j < 32; j++) {
            float4 v = *(const float4*)(src + j * 4);
            __half2 h0 = __floats2half2_rn(v.x, v.y);
            __half2 h1 = __floats2half2_rn(v.z, v.w);
            uint2 u;
            u.x = *(uint32_t*)&h0;
            u.y = *(uint32_t*)&h1;
            asm volatile("st.shared.v2.b32 [%0], {%1, %2};"
                         :: "r"(adst + j * 8), "r"(u.x), "r"(u.y) : "memory");
        }
    }

    const uint32_t a_off = (uint32_t)((wm * 64 + (lane & 7) + ((lane >> 3) & 1) * 8) * ASTR
                                     + ((lane >> 4) & 1) * 16);
    const uint32_t b_off = (uint32_t)((wn * 32 + (lane & 7) + ((lane >> 4) & 1) * 8) * STRB
                                     + ((lane >> 3) & 1) * 16);

    float acc[4][4][4];
#pragma unroll
    for (int i = 0; i < 4; i++)
#pragma unroll
        for (int j = 0; j < 4; j++)
#pragma unroll
            for (int e = 0; e < 4; e++) acc[i][j][e] = 0.f;

#pragma unroll 1
    for (int ktg = 0; ktg < 48; ++ktg) {
        if (ktg < 46)      CP_WAIT(2);
        else if (ktg == 46) CP_WAIT(1);
        else               CP_WAIT(0);
        __syncthreads();
        if (ktg + 3 < 48) {
            const int nt = ktg + 3;
            const int pnb = nt >> 3, pkt = nt & 7;
            const __half* b0 = g_wbt + (size_t)(pnb * 128 + r0) * 256 + pkt * 32 + kc * 8;
            const uint32_t bs = su + A_BYTES + (nt & 3) * BT_BYTES;
            cp16(bs + bo0, b0);
            cp16(bs + bo1, b0 + (size_t)64 * 256);
            CP_COMMIT();
        }

        const int nb  = ktg >> 3;
        const int kt  = ktg & 7;
        const uint32_t abase = su + a_off + (uint32_t)(kt * 64);
        const uint32_t bbase = su + A_BYTES + (ktg & 3) * BT_BYTES + b_off;
#pragma unroll
        for (int ks = 0; ks < 2; ks++) {
            uint32_t afr[4][4];
#pragma unroll
            for (int mf = 0; mf < 4; mf++)
                ldsm4(afr[mf][0], afr[mf][1], afr[mf][2], afr[mf][3],
                      abase + (uint32_t)(mf * 16 * ASTR + ks * 32));
            uint32_t bfr[4][2];
            ldsm4(bfr[0][0], bfr[0][1], bfr[1][0], bfr[1][1],
                  bbase + (uint32_t)(ks * 32));
            ldsm4(bfr[2][0], bfr[2][1], bfr[3][0], bfr[3][1],
                  bbase + (uint32_t)(16 * STRB + ks * 32));
#pragma unroll
            for (int mf = 0; mf < 4; mf++)
#pragma unroll
                for (int nf = 0; nf < 4; nf++)
                    mma_f16(acc[mf][nf], afr[mf], bfr[nf]);
        }

        if (kt == 7) {
            const int n0  = nb * 128;
            const int seg = n0 >> 8;
            __half* dst = (seg == 0) ? g_q : (seg == 1) ? g_k : g_v;
#pragma unroll
            for (int mf = 0; mf < 4; mf++) {
                const int row0 = wm * 64 + mf * 16 + (lane >> 2);
#pragma unroll
                for (int nf = 0; nf < 4; nf++) {
                    const int clg = n0 + wn * 32 + nf * 8 + (lane & 3) * 2;
                    const int cc  = clg & 255;
                    const int hh  = cc >> 5, d0 = cc & 31;
                    float* c4 = acc[mf][nf];
#pragma unroll
                    for (int half_i = 0; half_i < 2; half_i++) {
                        const int row = row0 + half_i * 8;
                        const int win = n2 + (row >> 6);
                        const int pp  = row & 63;
                        const float2 mwv = *(const float2*)(g_mw + pp * 768 + clg);
                        __half2 h2 = __floats2half2_rn(c4[half_i * 2 + 0] + mwv.x,
                                                       c4[half_i * 2 + 1] + mwv.y);
                        *(__half2*)(dst + (((size_t)win * NH + hh) * NTOK + pp) * HD + d0) = h2;
                    }
#pragma unroll
                    for (int e = 0; e < 4; e++) c4[e] = 0.f;
                }
            }
        }
    }
}

// ---------------------------------------------------------------------------
// Kernel B (FP16 MMA attention, register-resident softmax):
// block = (window, head), 128 thr / 4 warps; warp owns 16 ROWS end-to-end.
// ---------------------------------------------------------------------------
__global__ __launch_bounds__(128, 7) void attn_tc()
{
    __shared__ __half Qs[64][40];     // stride 80B
    __shared__ __half Ks[64][40];
    __shared__ __half Vs[64][40];
    __shared__ float  bsb[226];

    const int b = blockIdx.x;
    const int h = b & 7;
    const int n = b >> 3;
    const int tid  = threadIdx.x;
    const int lane = tid & 31;
    const int warp = tid >> 5;
    const size_t base = (size_t)b * (NTOK * HD);

    // Stage Q/K/V (fp16, 16B chunks) + bias table (contiguous, transposed)
    {
        const uint32_t sq = (uint32_t)__cvta_generic_to_shared(Qs);
        const uint32_t sk = (uint32_t)__cvta_generic_to_shared(Ks);
        const uint32_t sv = (uint32_t)__cvta_generic_to_shared(Vs);
#pragma unroll
        for (int it = 0; it < 2; it++) {
            const int idx = tid + it * 128;
            const int p  = idx >> 2;
            const int q4 = idx & 3;
            cp16(sq + (uint32_t)(p * STRB + q4 * 16), g_q + base + p * 32 + q4 * 8);
            cp16(sk + (uint32_t)(p * STRB + q4 * 16), g_k + base + p * 32 + q4 * 8);
            cp16(sv + (uint32_t)(p * STRB + q4 * 16), g_v + base + p * 32 + q4 * 8);
        }
        CP_COMMIT();
        const float* rb = g_rptT + h * 225;
        for (int i = tid; i < 225; i += 128) bsb[i] = rb[i];
        CP_WAIT(0);
    }
    __syncthreads();

    const int t = lane & 3, g = lane >> 2;
    const uint32_t sqb = (uint32_t)__cvta_generic_to_shared(Qs);
    const uint32_t skb = (uint32_t)__cvta_generic_to_shared(Ks);
    const uint32_t svb = (uint32_t)__cvta_generic_to_shared(Vs);

    const uint32_t arow = (lane & 7) + ((lane >> 3) & 1) * 8;
    const uint32_t alk  = ((lane >> 4) & 1) * 16;
    const uint32_t brow = (lane & 7) + ((lane >> 4) & 1) * 8;
    const uint32_t blk  = ((lane >> 3) & 1) * 16;

    // ---- QK^T: warp computes S[warp*16 .. +15, 0..63] ----
    float sa[8][4];
#pragma unroll
    for (int i = 0; i < 8; i++)
#pragma unroll
        for (int e = 0; e < 4; e++) sa[i][e] = 0.f;

#pragma unroll
    for (int ks = 0; ks < 2; ks++) {
        uint32_t af[4];
        ldsm4(af[0], af[1], af[2], af[3],
              sqb + (uint32_t)((warp * 16 + arow) * STRB + ks * 32) + alk);
#pragma unroll
        for (int bt = 0; bt < 4; bt++) {
            uint32_t bf[2][2];
            ldsm4(bf[0][0], bf[0][1], bf[1][0], bf[1][1],
                  skb + (uint32_t)((bt * 16 + brow) * STRB + ks * 32) + blk);
            mma_f16(sa[2 * bt],     af, bf[0]);
            mma_f16(sa[2 * bt + 1], af, bf[1]);
        }
    }

    // ---- bias add + row max (rows r0 = warp*16+g, r1 = r0+8) ----
    const int r0 = warp * 16 + g, r1 = r0 + 8;
    const int qy0 = r0 >> 3, qx0 = r0 & 7;
    const int qy1 = r1 >> 3, qx1 = r1 & 7;
    float mx0 = -1e30f, mx1 = -1e30f;
#pragma unroll
    for (int nt = 0; nt < 8; nt++) {
        const int c0 = nt * 8 + 2 * t, c1 = c0 + 1;
        const int ky0 = c0 >> 3, kx0 = c0 & 7;
        const int ky1 = c1 >> 3, kx1 = c1 & 7;
        sa[nt][0] += bsb[(qy0 - ky0 + 7) * 15 + (qx0 - kx0 + 7)];
        sa[nt][1] += bsb[(qy0 - ky1 + 7) * 15 + (qx0 - kx1 + 7)];
        sa[nt][2] += bsb[(qy1 - ky0 + 7) * 15 + (qx1 - kx0 + 7)];
        sa[nt][3] += bsb[(qy1 - ky1 + 7) * 15 + (qx1 - kx1 + 7)];
        mx0 = fmaxf(mx0, fmaxf(sa[nt][0], sa[nt][1]));
        mx1 = fmaxf(mx1, fmaxf(sa[nt][2], sa[nt][3]));
    }
    mx0 = fmaxf(mx0, __shfl_xor_sync(0xffffffffu, mx0, 1));
    mx0 = fmaxf(mx0, __shfl_xor_sync(0xffffffffu, mx0, 2));
    mx1 = fmaxf(mx1, __shfl_xor_sync(0xffffffffu, mx1, 1));
    mx1 = fmaxf(mx1, __shfl_xor_sync(0xffffffffu, mx1, 2));

    float sum0 = 0.f, sum1 = 0.f;
#pragma unroll
    for (int nt = 0; nt < 8; nt++) {
        sa[nt][0] = __expf(sa[nt][0] - mx0);
        sa[nt][1] = __expf(sa[nt][1] - mx0);
        sa[nt][2] = __expf(sa[nt][2] - mx1);
        sa[nt][3] = __expf(sa[nt][3] - mx1);
        sum0 += sa[nt][0] + sa[nt][1];
        sum1 += sa[nt][2] + sa[nt][3];
    }
    sum0 += __shfl_xor_sync(0xffffffffu, sum0, 1);
    sum0 += __shfl_xor_sync(0xffffffffu, sum0, 2);
    sum1 += __shfl_xor_sync(0xffffffffu, sum1, 1);
    sum1 += __shfl_xor_sync(0xffffffffu, sum1, 2);
    const float inv0 = 1.0f / sum0;
    const float inv1 = 1.0f / sum1;

    // ---- PV: P frags straight from registers; V via ldsm trans ----
    float oa[4][4];
#pragma unroll
    for (int i = 0; i < 4; i++)
#pragma unroll
        for (int e = 0; e < 4; e++) oa[i][e] = 0.f;

#pragma unroll
    for (int kt = 0; kt < 4; kt++) {
        __half2 p0 = __floats2half2_rn(sa[2 * kt][0] * inv0, sa[2 * kt][1] * inv0);
        __half2 p1 = __floats2half2_rn(sa[2 * kt][2] * inv1, sa[2 * kt][3] * inv1);
        __half2 p2 = __floats2half2_rn(sa[2 * kt + 1][0] * inv0, sa[2 * kt + 1][1] * inv0);
        __half2 p3 = __floats2half2_rn(sa[2 * kt + 1][2] * inv1, sa[2 * kt + 1][3] * inv1);
        uint32_t af2[4];
        af2[0] = *(uint32_t*)&p0;
        af2[1] = *(uint32_t*)&p1;
        af2[2] = *(uint32_t*)&p2;
        af2[3] = *(uint32_t*)&p3;
        uint32_t bf[4][2];
        ldsm4t(bf[0][0], bf[0][1], bf[1][0], bf[1][1],
               svb + (uint32_t)((kt * 16 + arow) * STRB) + alk);
        ldsm4t(bf[2][0], bf[2][1], bf[3][0], bf[3][1],
               svb + (uint32_t)((kt * 16 + arow) * STRB + 32) + alk);
#pragma unroll
        for (int nt = 0; nt < 4; nt++)
            mma_f16(oa[nt], af2, bf[nt]);
    }

    // ---- Write O (fp16): rows r0, r1; cols nt*8 + 2t ----
#pragma unroll
    for (int nt = 0; nt < 4; nt++) {
        const int col = nt * 8 + 2 * t;
        __half2 h0 = __floats2half2_rn(oa[nt][0], oa[nt][1]);
        __half2 h1 = __floats2half2_rn(oa[nt][2], oa[nt][3]);
        *(__half2*)(g_o + ((size_t)n * NTOK + r0) * C_DIM + h * HD + col) = h0;
        *(__half2*)(g_o + ((size_t)n * NTOK + r1) * C_DIM + h * HD + col) = h1;
    }
}

// ---------------------------------------------------------------------------
// Kernel C (FP16 MMA + ldmatrix): proj GEMM + inverse window scatter.
// grid = (2, 2048).
// ---------------------------------------------------------------------------
__global__ __launch_bounds__(256, 2) void proj_tc(
    const float* __restrict__ pb, float* __restrict__ out)
{
    extern __shared__ uint32_t smem[];
    const uint32_t su = (uint32_t)__cvta_generic_to_shared(smem);

    const int tid  = threadIdx.x;
    const int lane = tid & 31;
    const int warp = tid >> 5;
    const int wm   = warp >> 2;
    const int wn   = warp & 3;
    const int rbase = blockIdx.y * 128;
    const int n0    = blockIdx.x * 128;

    const int r0 = tid >> 2;
    const int kc = tid & 3;
    const __half* ap0 = g_o + (size_t)(rbase + r0) * 256 + kc * 8;
    const __half* ap1 = g_o + (size_t)(rbase + r0 + 64) * 256 + kc * 8;
    const uint32_t ao0 = (uint32_t)(r0 * STRB + kc * 16);
    const uint32_t ao1 = (uint32_t)((r0 + 64) * STRB + kc * 16);
    const __half* bp0 = g_pwt + (size_t)(n0 + r0) * 256 + kc * 8;
    const __half* bp1 = g_pwt + (size_t)(n0 + r0 + 64) * 256 + kc * 8;

    const uint32_t a_off = (uint32_t)((wm * 64 + (lane & 7) + ((lane >> 3) & 1) * 8) * STRB
                                     + ((lane >> 4) & 1) * 16);
    const uint32_t b_off = (uint32_t)((wn * 32 + (lane & 7) + ((lane >> 4) & 1) * 8) * STRB
                                     + ((lane >> 3) & 1) * 16);

    float acc[4][4][4];
#pragma unroll
    for (int i = 0; i < 4; i++)
#pragma unroll
        for (int j = 0; j < 4; j++)
#pragma unroll
            for (int e = 0; e < 4; e++) acc[i][j][e] = 0.f;

#pragma unroll
    for (int s = 0; s < 2; s++) {
        const int k0 = s * 32;
        cp16(su + s * TILE_STG + ao0, ap0 + k0);
        cp16(su + s * TILE_STG + ao1, ap1 + k0);
        cp16(su + PB_BASE + s * TILE_STG + ao0, bp0 + k0);
        cp16(su + PB_BASE + s * TILE_STG + ao1, bp1 + k0);
        CP_COMMIT();
    }

#pragma unroll 1
    for (int kt = 0; kt < 8; ++kt) {
        if (kt < 6) CP_WAIT(1); else CP_WAIT(0);
        __syncthreads();
        if (kt + 2 < 8) {
            const int s = (kt + 2) % NSTG;
            const int k0 = (kt + 2) * 32;
            cp16(su + s * TILE_STG + ao0, ap0 + k0);
            cp16(su + s * TILE_STG + ao1, ap1 + k0);
            cp16(su + PB_BASE + s * TILE_STG + ao0, bp0 + k0);
            cp16(su + PB_BASE + s * TILE_STG + ao1, bp1 + k0);
            CP_COMMIT();
        }

        const int buf = kt % NSTG;
        const uint32_t abase = su + buf * TILE_STG + a_off;
        const uint32_t bbase = su + PB_BASE + buf * TILE_STG + b_off;
#pragma unroll
        for (int ks = 0; ks < 2; ks++) {
            uint32_t afr[4][4];
#pragma unroll
            for (int mf = 0; mf < 4; mf++)
                ldsm4(afr[mf][0], afr[mf][1], afr[mf][2], afr[mf][3],
                      abase + (uint32_t)(mf * 16 * STRB + ks * 32));
            uint32_t bfr[4][2];
            ldsm4(bfr[0][0], bfr[0][1], bfr[1][0], bfr[1][1],
                  bbase + (uint32_t)(ks * 32));
            ldsm4(bfr[2][0], bfr[2][1], bfr[3][0], bfr[3][1],
                  bbase + (uint32_t)(16 * STRB + ks * 32));
#pragma unroll
            for (int mf = 0; mf < 4; mf++)
#pragma unroll
                for (int nf = 0; nf < 4; nf++)
                    mma_f16(acc[mf][nf], afr[mf], bfr[nf]);
        }
    }

#pragma unroll
    for (int mf = 0; mf < 4; mf++) {
        const int row0 = wm * 64 + mf * 16 + (lane >> 2);
#pragma unroll
        for (int nf = 0; nf < 4; nf++) {
            const int col = n0 + wn * 32 + nf * 8 + (lane & 3) * 2;
            const float b0 = pb[col], b1 = pb[col + 1];
            const float* c4 = acc[mf][nf];
#pragma unroll
            for (int half_i = 0; half_i < 2; half_i++) {
                const int grow = rbase + row0 + half_i * 8;
                const int win = grow >> 6;
                const int p   = grow & 63;
                const int t_idx = win >> 10, wh = (win >> 5) & 31, ww = win & 31;
                const int py = p >> 3, px = p & 7;
                const size_t pix =
                    (((size_t)t_idx * H_DIM + wh * PS + py) * W_DIM + ww * PS + px) * C_DIM;
                float2 v2;
                v2.x = c4[half_i * 2 + 0] + b0;
                v2.y = c4[half_i * 2 + 1] + b1;
                *(float2*)(out + pix + col) = v2;
            }
        }
    }
}

// ---------------------------------------------------------------------------
extern "C" void kernel_launch(void* const* d_in, const int* in_sizes, int n_in,
                              void* d_out, int out_size)
{
    const float* vid  = (const float*)d_in[0];
    const float* modu = (const float*)d_in[1];
    const float* wq   = (const float*)d_in[2];
    const float* bq   = (const float*)d_in[3];
    const float* wkv  = (const float*)d_in[4];
    const float* bkv  = (const float*)d_in[5];
    const float* pw   = (const float*)d_in[6];
    const float* pb   = (const float*)d_in[7];
    const float* rpt  = (const float*)d_in[8];
    float* out = (float*)d_out;

    cudaFuncSetAttribute(qkv_tc,  cudaFuncAttributeMaxDynamicSharedMemorySize, QKV_SMEM);
    cudaFuncSetAttribute(proj_tc, cudaFuncAttributeMaxDynamicSharedMemorySize, PROJ_SMEM);

    prep_w<<<1032, 256>>>(wq, wkv, pw, rpt);
    prep_modw<<<dim3(64, 3), 256>>>(modu, wq, bq, wkv, bkv);
    qkv_tc<<<2048, 256, QKV_SMEM>>>(vid);
    attn_tc<<<NWIN * NH, 128>>>();
    proj_tc<<<dim3(2, 2048), 256, PROJ_SMEM>>>(pb, out);
}

// round 14
// speedup vs baseline: 1.0805x; 1.0805x over previous
#include <cuda_runtime.h>
#include <cuda_fp16.h>
#include <math.h>
#include <stdint.h>

// Problem constants
#define T_DIM   4
#define H_DIM   256
#define W_DIM   256
#define C_DIM   256
#define PS      8
#define NH      8
#define HD      32
#define NTOK    64
#define NWIN    4096
#define NROWS   (NWIN * NTOK)

// Scratch (allocation-free rule: __device__ globals)
__device__ __half g_q[(size_t)NWIN * NH * NTOK * HD]; // [n][h][p][d]
__device__ __half g_k[(size_t)NWIN * NH * NTOK * HD];
__device__ __half g_v[(size_t)NWIN * NH * NTOK * HD];
__device__ __half g_o[(size_t)NROWS * C_DIM];         // [n][p][c]
__device__ __half g_wbt[768 * 256];                   // [n][k]: [wq*sc|wkv]^T
__device__ __half g_pwt[256 * 256];                   // [n][k]: proj_w^T
__device__ float  g_mw[64 * 768];                     // fp32: modu@W + bias (q scaled)
__device__ float  g_rptT[8 * 225];                    // bias table transposed [h][225]

// ---------------------------------------------------------------------------
__device__ __forceinline__ void mma_f16(float* c, const uint32_t* a, const uint32_t* b) {
    asm volatile(
        "mma.sync.aligned.m16n8k16.row.col.f32.f16.f16.f32 "
        "{%0,%1,%2,%3}, {%4,%5,%6,%7}, {%8,%9}, {%0,%1,%2,%3};"
        : "+f"(c[0]), "+f"(c[1]), "+f"(c[2]), "+f"(c[3])
        : "r"(a[0]), "r"(a[1]), "r"(a[2]), "r"(a[3]), "r"(b[0]), "r"(b[1]));
}
__device__ __forceinline__ void ldsm4(uint32_t& r0, uint32_t& r1, uint32_t& r2,
                                      uint32_t& r3, uint32_t addr) {
    asm volatile("ldmatrix.sync.aligned.m8n8.x4.shared.b16 {%0,%1,%2,%3}, [%4];"
        : "=r"(r0), "=r"(r1), "=r"(r2), "=r"(r3) : "r"(addr));
}
__device__ __forceinline__ void ldsm4t(uint32_t& r0, uint32_t& r1, uint32_t& r2,
                                       uint32_t& r3, uint32_t addr) {
    asm volatile("ldmatrix.sync.aligned.m8n8.x4.trans.shared.b16 {%0,%1,%2,%3}, [%4];"
        : "=r"(r0), "=r"(r1), "=r"(r2), "=r"(r3) : "r"(addr));
}
__device__ __forceinline__ void cp16(uint32_t s, const void* g) {
    asm volatile("cp.async.ca.shared.global [%0], [%1], 16;" :: "r"(s), "l"(g));
}
#define CP_COMMIT() asm volatile("cp.async.commit_group;" ::: "memory")
#define CP_WAIT(n)  asm volatile("cp.async.wait_group %0;" :: "n"(n) : "memory")

#define STRB 80                       // B / attn row stride bytes
// qkv smem: A resident + 4-stage B ring
#define ASTR 528                      // A row stride bytes (512 + 16 pad)
#define A_BYTES (128 * ASTR)          // 67584
#define BT_BYTES (128 * STRB)         // 10240 per B stage
#define QKV_SMEM (A_BYTES + 4 * BT_BYTES)   // 108544

// proj smem (3-stage, both operands streamed)
#define NSTG 3
#define TILE_STG (128 * STRB)
#define PB_BASE  (NSTG * TILE_STG)
#define PROJ_SMEM (2 * NSTG * TILE_STG)     // 61440

// ---------------------------------------------------------------------------
// Prep 1: weights -> fp16 transposed [n][k] (q-scale folded) + rpt transpose
// grid = 1032 x 256
// ---------------------------------------------------------------------------
__global__ __launch_bounds__(256) void prep_w(
    const float* __restrict__ wq, const float* __restrict__ wkv,
    const float* __restrict__ pw, const float* __restrict__ rpt)
{
    const float sc = 0.1767766952966369f; // 1/sqrt(32)
    int idx = blockIdx.x * 256 + threadIdx.x;
    if (idx < 196608) {
        int n = idx >> 8, k = idx & 255;
        float v = (n < 256) ? wq[k * 256 + n] * sc : wkv[k * 512 + (n - 256)];
        g_wbt[idx] = __float2half_rn(v);
    } else if (idx < 262144) {
        int j = idx - 196608;
        int n = j >> 8, k = j & 255;
        g_pwt[j] = __float2half_rn(pw[k * 256 + n]);
    } else {
        int j2 = idx - 262144;
        if (j2 < 1800) {
            int h = j2 / 225, i = j2 % 225;
            g_rptT[h * 225 + i] = rpt[(size_t)i * NH + h];
        }
    }
}

// ---------------------------------------------------------------------------
// Prep 2 (R12 form): modw[p][c] = modu[p]@W + bias. grid 64 x 256.
// ---------------------------------------------------------------------------
__global__ __launch_bounds__(256) void prep_modw(
    const float* __restrict__ modu,
    const float* __restrict__ wq,  const float* __restrict__ bq,
    const float* __restrict__ wkv, const float* __restrict__ bkv)
{
    __shared__ float m[256];
    const int p = blockIdx.x;
    m[threadIdx.x] = modu[p * 256 + threadIdx.x];
    __syncthreads();
    const float sc = 0.1767766952966369f;
#pragma unroll
    for (int rep = 0; rep < 3; rep++) {
        int c = rep * 256 + threadIdx.x;
        float s = 0.f;
        if (c < 256) {
            for (int k = 0; k < 256; k++) s = fmaf(m[k], wq[k * 256 + c], s);
            s = (s + bq[c]) * sc;
        } else {
            int cc = c - 256;
            for (int k = 0; k < 256; k++) s = fmaf(m[k], wkv[k * 512 + cc], s);
            s += bkv[cc];
        }
        g_mw[p * 768 + c] = s;
    }
}

// ---------------------------------------------------------------------------
// Kernel A (FP16 MMA, A-resident): X @ [wq|wkv], all 768 cols per CTA.
// 512 threads / 16 warps (4m x 4n), warp tile 32x32. grid = 2048.
// ---------------------------------------------------------------------------
__global__ __launch_bounds__(512, 2) void qkv_tc(const float* __restrict__ vid)
{
    extern __shared__ uint32_t smem[];
    const uint32_t su = (uint32_t)__cvta_generic_to_shared(smem);

    const int tid  = threadIdx.x;
    const int lane = tid & 31;
    const int warp = tid >> 5;        // 0..15
    const int wm   = warp >> 2;       // 0..3 -> rows wm*32
    const int wn   = warp & 3;        // 0..3 -> cols wn*32
    const int n2   = blockIdx.x * 2;

    // B cp.async mapping: ONE cp16 per thread per ktile (row r0, chunk kc)
    const int r0 = tid >> 2;          // 0..127
    const int kc = tid & 3;           // 0..3
    const uint32_t bo = (uint32_t)(r0 * STRB + kc * 16);

#pragma unroll
    for (int s = 0; s < 3; s++) {
        const __half* b0 = g_wbt + (size_t)r0 * 256 + s * 32 + kc * 8;
        cp16(su + A_BYTES + s * BT_BYTES + bo, b0);
        CP_COMMIT();
    }

    // A load: fp32 vid -> fp16 resident smem (each thread: 64 floats of one row)
    {
        const int ar = tid >> 2;          // row 0..127
        const int aq = tid & 3;           // quarter (64 floats)
        const int win = n2 + (ar >> 6);
        const int p   = ar & 63;
        const int ti = win >> 10, wh = (win >> 5) & 31, ww = win & 31;
        const float* src = vid +
            (((size_t)ti * H_DIM + wh * PS + (p >> 3)) * W_DIM + ww * PS + (p & 7)) * C_DIM
            + aq * 64;
        const uint32_t adst = su + (uint32_t)(ar * ASTR + aq * 128);
#pragma unroll
        for (int j = 0; j < 16; j++) {
            float4 v = *(const float4*)(src + j * 4);
            __half2 h0 = __floats2half2_rn(v.x, v.y);
            __half2 h1 = __floats2half2_rn(v.z, v.w);
            uint2 u;
            u.x = *(uint32_t*)&h0;
            u.y = *(uint32_t*)&h1;
            asm volatile("st.shared.v2.b32 [%0], {%1, %2};"
                         :: "r"(adst + j * 8), "r"(u.x), "r"(u.y) : "memory");
        }
    }

    const uint32_t a_off = (uint32_t)((wm * 32 + (lane & 7) + ((lane >> 3) & 1) * 8) * ASTR
                                     + ((lane >> 4) & 1) * 16);
    const uint32_t b_off = (uint32_t)((wn * 32 + (lane & 7) + ((lane >> 4) & 1) * 8) * STRB
                                     + ((lane >> 3) & 1) * 16);

    float acc[2][4][4];
#pragma unroll
    for (int i = 0; i < 2; i++)
#pragma unroll
        for (int j = 0; j < 4; j++)
#pragma unroll
            for (int e = 0; e < 4; e++) acc[i][j][e] = 0.f;

#pragma unroll 1
    for (int ktg = 0; ktg < 48; ++ktg) {
        if (ktg < 46)       CP_WAIT(2);
        else if (ktg == 46) CP_WAIT(1);
        else                CP_WAIT(0);
        __syncthreads();
        if (ktg + 3 < 48) {
            const int nt = ktg + 3;
            const int pnb = nt >> 3, pkt = nt & 7;
            const __half* b0 = g_wbt + (size_t)(pnb * 128 + r0) * 256 + pkt * 32 + kc * 8;
            cp16(su + A_BYTES + (nt & 3) * BT_BYTES + bo, b0);
            CP_COMMIT();
        }

        const int nb  = ktg >> 3;
        const int kt  = ktg & 7;
        const uint32_t abase = su + a_off + (uint32_t)(kt * 64);
        const uint32_t bbase = su + A_BYTES + (ktg & 3) * BT_BYTES + b_off;
#pragma unroll
        for (int ks = 0; ks < 2; ks++) {
            uint32_t afr[2][4];
#pragma unroll
            for (int mf = 0; mf < 2; mf++)
                ldsm4(afr[mf][0], afr[mf][1], afr[mf][2], afr[mf][3],
                      abase + (uint32_t)(mf * 16 * ASTR + ks * 32));
            uint32_t bfr[4][2];
            ldsm4(bfr[0][0], bfr[0][1], bfr[1][0], bfr[1][1],
                  bbase + (uint32_t)(ks * 32));
            ldsm4(bfr[2][0], bfr[2][1], bfr[3][0], bfr[3][1],
                  bbase + (uint32_t)(16 * STRB + ks * 32));
#pragma unroll
            for (int mf = 0; mf < 2; mf++)
#pragma unroll
                for (int nf = 0; nf < 4; nf++)
                    mma_f16(acc[mf][nf], afr[mf], bfr[nf]);
        }

        if (kt == 7) {
            const int n0  = nb * 128;
            const int seg = n0 >> 8;
            __half* dst = (seg == 0) ? g_q : (seg == 1) ? g_k : g_v;
#pragma unroll
            for (int mf = 0; mf < 2; mf++) {
                const int row0 = wm * 32 + mf * 16 + (lane >> 2);
#pragma unroll
                for (int nf = 0; nf < 4; nf++) {
                    const int clg = n0 + wn * 32 + nf * 8 + (lane & 3) * 2;
                    const int cc  = clg & 255;
                    const int hh  = cc >> 5, d0 = cc & 31;
                    float* c4 = acc[mf][nf];
#pragma unroll
                    for (int half_i = 0; half_i < 2; half_i++) {
                        const int row = row0 + half_i * 8;
                        const int win = n2 + (row >> 6);
                        const int pp  = row & 63;
                        const float2 mwv = *(const float2*)(g_mw + pp * 768 + clg);
                        __half2 h2 = __floats2half2_rn(c4[half_i * 2 + 0] + mwv.x,
                                                       c4[half_i * 2 + 1] + mwv.y);
                        *(__half2*)(dst + (((size_t)win * NH + hh) * NTOK + pp) * HD + d0) = h2;
                    }
#pragma unroll
                    for (int e = 0; e < 4; e++) c4[e] = 0.f;
                }
            }
        }
    }
}

// ---------------------------------------------------------------------------
// Kernel B (FP16 MMA attention, register-resident softmax).
// ---------------------------------------------------------------------------
__global__ __launch_bounds__(128, 7) void attn_tc()
{
    __shared__ __half Qs[64][40];
    __shared__ __half Ks[64][40];
    __shared__ __half Vs[64][40];
    __shared__ float  bsb[226];

    const int b = blockIdx.x;
    const int h = b & 7;
    const int n = b >> 3;
    const int tid  = threadIdx.x;
    const int lane = tid & 31;
    const int warp = tid >> 5;
    const size_t base = (size_t)b * (NTOK * HD);

    {
        const uint32_t sq = (uint32_t)__cvta_generic_to_shared(Qs);
        const uint32_t sk = (uint32_t)__cvta_generic_to_shared(Ks);
        const uint32_t sv = (uint32_t)__cvta_generic_to_shared(Vs);
#pragma unroll
        for (int it = 0; it < 2; it++) {
            const int idx = tid + it * 128;
            const int p  = idx >> 2;
            const int q4 = idx & 3;
            cp16(sq + (uint32_t)(p * STRB + q4 * 16), g_q + base + p * 32 + q4 * 8);
            cp16(sk + (uint32_t)(p * STRB + q4 * 16), g_k + base + p * 32 + q4 * 8);
            cp16(sv + (uint32_t)(p * STRB + q4 * 16), g_v + base + p * 32 + q4 * 8);
        }
        CP_COMMIT();
        const float* rb = g_rptT + h * 225;
        for (int i = tid; i < 225; i += 128) bsb[i] = rb[i];
        CP_WAIT(0);
    }
    __syncthreads();

    const int t = lane & 3, g = lane >> 2;
    const uint32_t sqb = (uint32_t)__cvta_generic_to_shared(Qs);
    const uint32_t skb = (uint32_t)__cvta_generic_to_shared(Ks);
    const uint32_t svb = (uint32_t)__cvta_generic_to_shared(Vs);

    const uint32_t arow = (lane & 7) + ((lane >> 3) & 1) * 8;
    const uint32_t alk  = ((lane >> 4) & 1) * 16;
    const uint32_t brow = (lane & 7) + ((lane >> 4) & 1) * 8;
    const uint32_t blk  = ((lane >> 3) & 1) * 16;

    float sa[8][4];
#pragma unroll
    for (int i = 0; i < 8; i++)
#pragma unroll
        for (int e = 0; e < 4; e++) sa[i][e] = 0.f;

#pragma unroll
    for (int ks = 0; ks < 2; ks++) {
        uint32_t af[4];
        ldsm4(af[0], af[1], af[2], af[3],
              sqb + (uint32_t)((warp * 16 + arow) * STRB + ks * 32) + alk);
#pragma unroll
        for (int bt = 0; bt < 4; bt++) {
            uint32_t bf[2][2];
            ldsm4(bf[0][0], bf[0][1], bf[1][0], bf[1][1],
                  skb + (uint32_t)((bt * 16 + brow) * STRB + ks * 32) + blk);
            mma_f16(sa[2 * bt],     af, bf[0]);
            mma_f16(sa[2 * bt + 1], af, bf[1]);
        }
    }

    const int r0 = warp * 16 + g, r1 = r0 + 8;
    const int qy0 = r0 >> 3, qx0 = r0 & 7;
    const int qy1 = r1 >> 3, qx1 = r1 & 7;
    float mx0 = -1e30f, mx1 = -1e30f;
#pragma unroll
    for (int nt = 0; nt < 8; nt++) {
        const int c0 = nt * 8 + 2 * t, c1 = c0 + 1;
        const int ky0 = c0 >> 3, kx0 = c0 & 7;
        const int ky1 = c1 >> 3, kx1 = c1 & 7;
        sa[nt][0] += bsb[(qy0 - ky0 + 7) * 15 + (qx0 - kx0 + 7)];
        sa[nt][1] += bsb[(qy0 - ky1 + 7) * 15 + (qx0 - kx1 + 7)];
        sa[nt][2] += bsb[(qy1 - ky0 + 7) * 15 + (qx1 - kx0 + 7)];
        sa[nt][3] += bsb[(qy1 - ky1 + 7) * 15 + (qx1 - kx1 + 7)];
        mx0 = fmaxf(mx0, fmaxf(sa[nt][0], sa[nt][1]));
        mx1 = fmaxf(mx1, fmaxf(sa[nt][2], sa[nt][3]));
    }
    mx0 = fmaxf(mx0, __shfl_xor_sync(0xffffffffu, mx0, 1));
    mx0 = fmaxf(mx0, __shfl_xor_sync(0xffffffffu, mx0, 2));
    mx1 = fmaxf(mx1, __shfl_xor_sync(0xffffffffu, mx1, 1));
    mx1 = fmaxf(mx1, __shfl_xor_sync(0xffffffffu, mx1, 2));

    float sum0 = 0.f, sum1 = 0.f;
#pragma unroll
    for (int nt = 0; nt < 8; nt++) {
        sa[nt][0] = __expf(sa[nt][0] - mx0);
        sa[nt][1] = __expf(sa[nt][1] - mx0);
        sa[nt][2] = __expf(sa[nt][2] - mx1);
        sa[nt][3] = __expf(sa[nt][3] - mx1);
        sum0 += sa[nt][0] + sa[nt][1];
        sum1 += sa[nt][2] + sa[nt][3];
    }
    sum0 += __shfl_xor_sync(0xffffffffu, sum0, 1);
    sum0 += __shfl_xor_sync(0xffffffffu, sum0, 2);
    sum1 += __shfl_xor_sync(0xffffffffu, sum1, 1);
    sum1 += __shfl_xor_sync(0xffffffffu, sum1, 2);
    const float inv0 = 1.0f / sum0;
    const float inv1 = 1.0f / sum1;

    float oa[4][4];
#pragma unroll
    for (int i = 0; i < 4; i++)
#pragma unroll
        for (int e = 0; e < 4; e++) oa[i][e] = 0.f;

#pragma unroll
    for (int kt = 0; kt < 4; kt++) {
        __half2 p0 = __floats2half2_rn(sa[2 * kt][0] * inv0, sa[2 * kt][1] * inv0);
        __half2 p1 = __floats2half2_rn(sa[2 * kt][2] * inv1, sa[2 * kt][3] * inv1);
        __half2 p2 = __floats2half2_rn(sa[2 * kt + 1][0] * inv0, sa[2 * kt + 1][1] * inv0);
        __half2 p3 = __floats2half2_rn(sa[2 * kt + 1][2] * inv1, sa[2 * kt + 1][3] * inv1);
        uint32_t af2[4];
        af2[0] = *(uint32_t*)&p0;
        af2[1] = *(uint32_t*)&p1;
        af2[2] = *(uint32_t*)&p2;
        af2[3] = *(uint32_t*)&p3;
        uint32_t bf[4][2];
        ldsm4t(bf[0][0], bf[0][1], bf[1][0], bf[1][1],
               svb + (uint32_t)((kt * 16 + arow) * STRB) + alk);
        ldsm4t(bf[2][0], bf[2][1], bf[3][0], bf[3][1],
               svb + (uint32_t)((kt * 16 + arow) * STRB + 32) + alk);
#pragma unroll
        for (int nt = 0; nt < 4; nt++)
            mma_f16(oa[nt], af2, bf[nt]);
    }

#pragma unroll
    for (int nt = 0; nt < 4; nt++) {
        const int col = nt * 8 + 2 * t;
        __half2 h0 = __floats2half2_rn(oa[nt][0], oa[nt][1]);
        __half2 h1 = __floats2half2_rn(oa[nt][2], oa[nt][3]);
        *(__half2*)(g_o + ((size_t)n * NTOK + r0) * C_DIM + h * HD + col) = h0;
        *(__half2*)(g_o + ((size_t)n * NTOK + r1) * C_DIM + h * HD + col) = h1;
    }
}

// ---------------------------------------------------------------------------
// Kernel C (FP16 MMA + ldmatrix): proj GEMM + inverse window scatter.
// grid = (2, 2048).
// ---------------------------------------------------------------------------
__global__ __launch_bounds__(256, 2) void proj_tc(
    const float* __restrict__ pb, float* __restrict__ out)
{
    extern __shared__ uint32_t smem[];
    const uint32_t su = (uint32_t)__cvta_generic_to_shared(smem);

    const int tid  = threadIdx.x;
    const int lane = tid & 31;
    const int warp = tid >> 5;
    const int wm   = warp >> 2;
    const int wn   = warp & 3;
    const int rbase = blockIdx.y * 128;
    const int n0    = blockIdx.x * 128;

    const int r0 = tid >> 2;
    const int kc = tid & 3;
    const __half* ap0 = g_o + (size_t)(rbase + r0) * 256 + kc * 8;
    const __half* ap1 = g_o + (size_t)(rbase + r0 + 64) * 256 + kc * 8;
    const uint32_t ao0 = (uint32_t)(r0 * STRB + kc * 16);
    const uint32_t ao1 = (uint32_t)((r0 + 64) * STRB + kc * 16);
    const __half* bp0 = g_pwt + (size_t)(n0 + r0) * 256 + kc * 8;
    const __half* bp1 = g_pwt + (size_t)(n0 + r0 + 64) * 256 + kc * 8;

    const uint32_t a_off = (uint32_t)((wm * 64 + (lane & 7) + ((lane >> 3) & 1) * 8) * STRB
                                     + ((lane >> 4) & 1) * 16);
    const uint32_t b_off = (uint32_t)((wn * 32 + (lane & 7) + ((lane >> 4) & 1) * 8) * STRB
                                     + ((lane >> 3) & 1) * 16);

    float acc[4][4][4];
#pragma unroll
    for (int i = 0; i < 4; i++)
#pragma unroll
        for (int j = 0; j < 4; j++)
#pragma unroll
            for (int e = 0; e < 4; e++) acc[i][j][e] = 0.f;

#pragma unroll
    for (int s = 0; s < 2; s++) {
        const int k0 = s * 32;
        cp16(su + s * TILE_STG + ao0, ap0 + k0);
        cp16(su + s * TILE_STG + ao1, ap1 + k0);
        cp16(su + PB_BASE + s * TILE_STG + ao0, bp0 + k0);
        cp16(su + PB_BASE + s * TILE_STG + ao1, bp1 + k0);
        CP_COMMIT();
    }

#pragma unroll 1
    for (int kt = 0; kt < 8; ++kt) {
        if (kt < 6) CP_WAIT(1); else CP_WAIT(0);
        __syncthreads();
        if (kt + 2 < 8) {
            const int s = (kt + 2) % NSTG;
            const int k0 = (kt + 2) * 32;
            cp16(su + s * TILE_STG + ao0, ap0 + k0);
            cp16(su + s * TILE_STG + ao1, ap1 + k0);
            cp16(su + PB_BASE + s * TILE_STG + ao0, bp0 + k0);
            cp16(su + PB_BASE + s * TILE_STG + ao1, bp1 + k0);
            CP_COMMIT();
        }

        const int buf = kt % NSTG;
        const uint32_t abase = su + buf * TILE_STG + a_off;
        const uint32_t bbase = su + PB_BASE + buf * TILE_STG + b_off;
#pragma unroll
        for (int ks = 0; ks < 2; ks++) {
            uint32_t afr[4][4];
#pragma unroll
            for (int mf = 0; mf < 4; mf++)
                ldsm4(afr[mf][0], afr[mf][1], afr[mf][2], afr[mf][3],
                      abase + (uint32_t)(mf * 16 * STRB + ks * 32));
            uint32_t bfr[4][2];
            ldsm4(bfr[0][0], bfr[0][1], bfr[1][0], bfr[1][1],
                  bbase + (uint32_t)(ks * 32));
            ldsm4(bfr[2][0], bfr[2][1], bfr[3][0], bfr[3][1],
                  bbase + (uint32_t)(16 * STRB + ks * 32));
#pragma unroll
            for (int mf = 0; mf < 4; mf++)
#pragma unroll
                for (int nf = 0; nf < 4; nf++)
                    mma_f16(acc[mf][nf], afr[mf], bfr[nf]);
        }
    }

#pragma unroll
    for (int mf = 0; mf < 4; mf++) {
        const int row0 = wm * 64 + mf * 16 + (lane >> 2);
#pragma unroll
        for (int nf = 0; nf < 4; nf++) {
            const int col = n0 + wn * 32 + nf * 8 + (lane & 3) * 2;
            const float b0 = pb[col], b1 = pb[col + 1];
            const float* c4 = acc[mf][nf];
#pragma unroll
            for (int half_i = 0; half_i < 2; half_i++) {
                const int grow = rbase + row0 + half_i * 8;
                const int win = grow >> 6;
                const int p   = grow & 63;
                const int t_idx = win >> 10, wh = (win >> 5) & 31, ww = win & 31;
                const int py = p >> 3, px = p & 7;
                const size_t pix =
                    (((size_t)t_idx * H_DIM + wh * PS + py) * W_DIM + ww * PS + px) * C_DIM;
                float2 v2;
                v2.x = c4[half_i * 2 + 0] + b0;
                v2.y = c4[half_i * 2 + 1] + b1;
                *(float2*)(out + pix + col) = v2;
            }
        }
    }
}

// ---------------------------------------------------------------------------
extern "C" void kernel_launch(void* const* d_in, const int* in_sizes, int n_in,
                              void* d_out, int out_size)
{
    const float* vid  = (const float*)d_in[0];
    const float* modu = (const float*)d_in[1];
    const float* wq   = (const float*)d_in[2];
    const float* bq   = (const float*)d_in[3];
    const float* wkv  = (const float*)d_in[4];
    const float* bkv  = (const float*)d_in[5];
    const float* pw   = (const float*)d_in[6];
    const float* pb   = (const float*)d_in[7];
    const float* rpt  = (const float*)d_in[8];
    float* out = (float*)d_out;

    cudaFuncSetAttribute(qkv_tc,  cudaFuncAttributeMaxDynamicSharedMemorySize, QKV_SMEM);
    cudaFuncSetAttribute(proj_tc, cudaFuncAttributeMaxDynamicSharedMemorySize, PROJ_SMEM);

    prep_w<<<1032, 256>>>(wq, wkv, pw, rpt);
    prep_modw<<<64, 256>>>(modu, wq, bq, wkv, bkv);
    qkv_tc<<<2048, 512, QKV_SMEM>>>(vid);
    attn_tc<<<NWIN * NH, 128>>>();
    proj_tc<<<dim3(2, 2048), 256, PROJ_SMEM>>>(pb, out);
}